// round 17
// baseline (speedup 1.0000x reference)
#include <cuda_runtime.h>
#include <cstdint>

#define Bn 8
#define Tn 100
#define BT 800
#define NTHR 320
#define NWARP 10
#define NBLK 443
#define PER 226                 // 443*226 = 100118 >= 100000
#define NPAIR 113               // max pairs per b (padded even)
#define PB (NPAIR * 32)         // 3616 B per b: {x0,x1|y0,y1|z0,z1|rm0,rm1}/pair
#define PAIR_BYTES (Bn * PB)    // 28928
#define MARGINF 0.1f
#define THRESHF 0.5f
#define Nn 100000

// Zero-initialized device state; last block resets -> replay-safe.
// cmax >= 0 so raw float bits are unsigned-monotone; bits(0.f)==0 matches init.
__device__ unsigned int g_key[BT];
__device__ unsigned int g_done;

__device__ __forceinline__ uint32_t smem_u32(const void* p) {
    uint32_t a;
    asm("{ .reg .u64 t; cvta.to.shared.u64 t, %1; cvt.u32.u64 %0, t; }"
        : "=r"(a) : "l"(p));
    return a;
}

__global__ void __launch_bounds__(NTHR, 3) kMain(
    const float* __restrict__ outputs,      // (8,100,3)
    const float* __restrict__ c2ws,         // (8,4,4)
    const float* __restrict__ sscales,      // (8,)
    const float* __restrict__ means,        // (100000,3)
    const float* __restrict__ scales,       // (100000,3)
    float* __restrict__ out)
{
    extern __shared__ char sdyn[];          // 28928 B: per-b 32-B pair blocks

    __shared__ float4   s_r4[BT];           // {rx,ry,rz,r2} per bt  (12800 B)
    __shared__ unsigned s_key[BT];          // per-block result keys (3200 B)
    __shared__ float s_lo[Bn * 3], s_hi[Bn * 3];
    __shared__ int   s_cnt[Bn];
    __shared__ int   s_pref[Bn + 1];
    __shared__ float s_red[NWARP];
    __shared__ int   s_last;

    const int tid = threadIdx.x;

    // ---- phase 1: retrajs into s_r4; init counters/keys -----------------
    for (int bt = tid; bt < BT; bt += NTHR) {
        int bb = bt / Tn;
        float ssb = sscales[bb];
        const float* c = c2ws + bb * 16;
        float o0 = outputs[bt * 3 + 0], o1 = outputs[bt * 3 + 1], o2 = outputs[bt * 3 + 2];
        float rx = fmaf(ssb, o0 * c[0] + o1 * c[1] + o2 * c[2],  c[3]);
        float ry = fmaf(ssb, o0 * c[4] + o1 * c[5] + o2 * c[6],  c[7]);
        float rz = fmaf(ssb, o0 * c[8] + o1 * c[9] + o2 * c[10], c[11]);
        float r2 = fmaf(rx, rx, fmaf(ry, ry, rz * rz));
        s_r4[bt] = make_float4(rx, ry, rz, r2);
    }
    if (tid < Bn) s_cnt[tid] = 0;
    for (int i = tid; i < BT; i += NTHR) s_key[i] = 0u;
    __syncthreads();

    // ---- phase 2: per-b boxes, 8 lanes per (b,e) ------------------------
    if (tid < Bn * 3 * 8) {                 // 192 threads, warps 0-5
        int be = tid / 8, l = tid % 8;
        int bb = be / 3, e = be % 3;
        const float* s_rf = (const float*)s_r4;
        float lo = 3.4e38f, hi = -3.4e38f;
        for (int t = l; t < Tn; t += 8) {
            float v = s_rf[(bb * Tn + t) * 4 + e];
            lo = fminf(lo, v); hi = fmaxf(hi, v);
        }
#pragma unroll
        for (int o = 4; o > 0; o >>= 1) {   // xor stays inside 8-lane group
            lo = fminf(lo, __shfl_xor_sync(0xffffffffu, lo, o));
            hi = fmaxf(hi, __shfl_xor_sync(0xffffffffu, hi, o));
        }
        if (l == 0) {
            float thres = THRESHF * sscales[0];
            s_lo[be] = lo - thres;
            s_hi[be] = hi + thres;
        }
    }
    __syncthreads();

    // ---- phase 3: stage slice, compacted per-b (warps 0-7) --------------
    if (tid < 256) {                          // full warps only (ballot-safe)
        int n0 = blockIdx.x * PER;
        int cnt_here = min(Nn - n0, PER);     // 108..226
        bool act = tid < cnt_here;
        float mx = 0.f, my = 0.f, mz = 0.f, radM = 0.f;
        if (act) {
            int n = n0 + tid;
            mx = means[n * 3 + 0]; my = means[n * 3 + 1]; mz = means[n * 3 + 2];
            float a0 = scales[n * 3 + 0], a1 = scales[n * 3 + 1], a2 = scales[n * 3 + 2];
            radM = fmaxf(a0, fmaxf(a1, a2)) + MARGINF;
        }
        unsigned lmask = (1u << (tid & 31)) - 1u;
#pragma unroll
        for (int bb = 0; bb < Bn; bb++) {
            bool in = act &&
                mx >= s_lo[bb * 3 + 0] && mx <= s_hi[bb * 3 + 0] &&
                my >= s_lo[bb * 3 + 1] && my <= s_hi[bb * 3 + 1] &&
                mz >= s_lo[bb * 3 + 2] && mz <= s_hi[bb * 3 + 2];
            unsigned bal = __ballot_sync(0xffffffffu, in);
            if (bal) {
                int leader = __ffs(bal) - 1;
                int base = 0;
                if ((tid & 31) == leader) base = atomicAdd(&s_cnt[bb], __popc(bal));
                base = __shfl_sync(0xffffffffu, base, leader);
                if (in) {
                    int i = base + __popc(bal & lmask);
                    char* pbp = sdyn + bb * PB + (i >> 1) * 32 + (i & 1) * 4;
                    *(float*)(pbp +  0) = mx;
                    *(float*)(pbp +  8) = my;
                    *(float*)(pbp + 16) = mz;
                    *(float*)(pbp + 24) = radM;
                }
            }
        }
    }
    __syncthreads();

    // ---- phase 4: pad odd counts (max is idempotent) ---------------------
    if (tid < Bn) {
        int c = s_cnt[tid];
        if (c & 1) {
            int i = c - 1;
            char* src = sdyn + tid * PB + (i >> 1) * 32 + (i & 1) * 4;
            char* dst = sdyn + tid * PB + (c >> 1) * 32 + (c & 1) * 4;
            *(float*)(dst +  0) = *(float*)(src +  0);
            *(float*)(dst +  8) = *(float*)(src +  8);
            *(float*)(dst + 16) = *(float*)(src + 16);
            *(float*)(dst + 24) = *(float*)(src + 24);
            s_cnt[tid] = c + 1;
        }
    }
    __syncthreads();
    if (tid == 0) {
        int p = 0;
        s_pref[0] = 0;
#pragma unroll
        for (int bb = 0; bb < Bn; bb++) { p += s_cnt[bb] >> 1; s_pref[bb + 1] = p; }
    }
    __syncthreads();

    // ---- phase 5: warp-balanced main loop --------------------------------
    // Warp w takes pair range [w*TP/10,(w+1)*TP/10) of the concatenated per-b
    // pair lists; every lane processes every pair against its own 4 t's.
    {
        const int w = tid >> 5, l = tid & 31;
        const int TP = s_pref[Bn];
        int idx = (w * TP) / NWARP;
        const int end = ((w + 1) * TP) / NWARP;
        // lane's 4 t slots; slot 3 duplicates t=l-4 when l+96 >= 100 (idempotent)
        const int t0 = l, t1 = l + 32, t2 = l + 64, t3 = (l + 96 < Tn) ? l + 96 : l - 4;
        const uint32_t base = smem_u32(sdyn);
        int b = 0;
        float c0 = 0.f, c1 = 0.f, c2 = 0.f, c3 = 0.f;
        while (idx < end) {
            while (idx >= s_pref[b + 1]) b++;
            const int lo = idx - s_pref[b];
            const int hi = min(end, s_pref[b + 1]) - s_pref[b];
            // load this b's t-constants into packed regs
            unsigned long long X[4], Y[4], Z[4], R[4];
            {
                const int tk[4] = { t0, t1, t2, t3 };
#pragma unroll
                for (int k = 0; k < 4; k++) {
                    float4 r4 = s_r4[b * Tn + tk[k]];
                    float nx = -2.f * r4.x, ny = -2.f * r4.y, nz = -2.f * r4.z;
                    asm("mov.b64 %0, {%1,%1};" : "=l"(X[k]) : "f"(nx));
                    asm("mov.b64 %0, {%1,%1};" : "=l"(Y[k]) : "f"(ny));
                    asm("mov.b64 %0, {%1,%1};" : "=l"(Z[k]) : "f"(nz));
                    asm("mov.b64 %0, {%1,%1};" : "=l"(R[k]) : "f"(r4.w));
                }
            }
            uint32_t addr = base + b * PB + lo * 32;
#pragma unroll 2
            for (int i = lo; i < hi; i++, addr += 32) {
                unsigned long long xx, yy, zz, rp, mm;
                float rm0, rm1;
                asm("ld.shared.v2.b64 {%0,%1}, [%2];" : "=l"(xx), "=l"(yy) : "r"(addr));
                asm("ld.shared.v2.b64 {%0,%1}, [%2];" : "=l"(zz), "=l"(rp) : "r"(addr + 16));
                asm("mov.b64 {%0,%1}, %2;" : "=f"(rm0), "=f"(rm1) : "l"(rp));
                asm("mul.rn.f32x2 %0, %1, %2;"     : "=l"(mm) : "l"(xx), "l"(xx));
                asm("fma.rn.f32x2 %0, %1, %2, %3;" : "=l"(mm) : "l"(yy), "l"(yy), "l"(mm));
                asm("fma.rn.f32x2 %0, %1, %2, %3;" : "=l"(mm) : "l"(zz), "l"(zz), "l"(mm));
#pragma unroll
                for (int k = 0; k < 4; k++) {
                    unsigned long long q, p;
                    asm("fma.rn.f32x2 %0, %1, %2, %3;" : "=l"(q) : "l"(xx), "l"(X[k]), "l"(mm));
                    asm("fma.rn.f32x2 %0, %1, %2, %3;" : "=l"(q) : "l"(yy), "l"(Y[k]), "l"(q));
                    asm("fma.rn.f32x2 %0, %1, %2, %3;" : "=l"(q) : "l"(zz), "l"(Z[k]), "l"(q));
                    asm("add.rn.f32x2 %0, %1, %2;"     : "=l"(p) : "l"(q),  "l"(R[k]));
                    float d2a, d2b, da, db;
                    asm("mov.b64 {%0,%1}, %2;" : "=f"(d2a), "=f"(d2b) : "l"(p));
                    // negative d2 (cancellation) -> NaN, dropped by fmaxf
                    asm("sqrt.approx.f32 %0, %1;" : "=f"(da) : "f"(d2a));
                    asm("sqrt.approx.f32 %0, %1;" : "=f"(db) : "f"(d2b));
                    float ck = (k == 0) ? c0 : (k == 1) ? c1 : (k == 2) ? c2 : c3;
                    ck = fmaxf(ck, rm0 - da);
                    ck = fmaxf(ck, rm1 - db);
                    if (k == 0) c0 = ck; else if (k == 1) c1 = ck;
                    else if (k == 2) c2 = ck; else c3 = ck;
                }
            }
            // commit this b's accumulators (lane-distinct smem addresses)
            if (c0 > 0.f) atomicMax(&s_key[b * Tn + t0], __float_as_uint(c0));
            if (c1 > 0.f) atomicMax(&s_key[b * Tn + t1], __float_as_uint(c1));
            if (c2 > 0.f) atomicMax(&s_key[b * Tn + t2], __float_as_uint(c2));
            if (c3 > 0.f) atomicMax(&s_key[b * Tn + t3], __float_as_uint(c3));
            c0 = c1 = c2 = c3 = 0.f;
            idx = s_pref[b] + hi;
        }
    }
    __syncthreads();

    // ---- phase 6: flush block keys to global -----------------------------
    for (int i = tid; i < BT; i += NTHR) {
        unsigned v = s_key[i];
        if (v) atomicMax(&g_key[i], v);
    }

    // ---- phase 7: grid-wide finalize via last-block pattern --------------
    __threadfence();
    __syncthreads();
    if (tid == 0) s_last = (atomicAdd(&g_done, 1u) == (unsigned)(NBLK - 1));
    __syncthreads();
    if (s_last) {
        float v = 0.f;
        for (int i = tid; i < BT; i += NTHR)
            v += __uint_as_float(atomicExch(&g_key[i], 0u));   // read + reset
        int w = tid >> 5, l = tid & 31;
#pragma unroll
        for (int o = 16; o > 0; o >>= 1) v += __shfl_xor_sync(0xffffffffu, v, o);
        if (l == 0) s_red[w] = v;
        __syncthreads();
        if (tid < 32) {
            float x = (tid < NWARP) ? s_red[tid] : 0.f;
#pragma unroll
            for (int o = 16; o > 0; o >>= 1) x += __shfl_xor_sync(0xffffffffu, x, o);
            if (tid == 0) {
                out[0] = x / (float)BT;
                g_done = 0u;
            }
        }
    }
}

extern "C" void kernel_launch(void* const* d_in, const int* in_sizes, int n_in,
                              void* d_out, int out_size) {
    const float* outputs      = (const float*)d_in[0];
    const float* c2ws         = (const float*)d_in[1];
    const float* scene_scales = (const float*)d_in[2];
    const float* means        = (const float*)d_in[3];
    const float* scales       = (const float*)d_in[4];
    float* out = (float*)d_out;

    kMain<<<NBLK, NTHR, (size_t)PAIR_BYTES>>>(outputs, c2ws, scene_scales,
                                              means, scales, out);
}